// round 16
// baseline (speedup 1.0000x reference)
#include <cuda_runtime.h>

#define BB 64
#define CC 768
#define SS 8
#define HH 28
#define WW 28
#define HW 784
#define LEARNED_SIZE (BB*CC*SS)   /* 393216 */
#define MASK_SIZE    (BB*SS*HW)   /* 401408 */

#define CGRP 16                   /* channel groups per batch for conv */
#define CH_PER (CC/CGRP)          /* 48 channels per CTA */

#define PSTRIDE 36                /* padded plane row stride */
#define PLANE_SZ (30*PSTRIDE)
#define WALL_SZ (CH_PER*72)       /* 3456 floats: [ci][t][s] */

typedef unsigned long long u64;

// partials: [CGRP][B][S][HW] — written with plain STG.128, reduced afterwards
__device__ float g_partial[(size_t)CGRP * BB * SS * HW];

__device__ __forceinline__ u64 pk2(float lo, float hi) {
    u64 r; asm("mov.b64 %0, {%1,%2};" : "=l"(r) : "f"(lo), "f"(hi)); return r;
}
__device__ __forceinline__ void fma2(u64 &d, u64 a, u64 b) {
    asm("fma.rn.f32x2 %0, %1, %2, %0;" : "+l"(d) : "l"(a), "l"(b));
}
__device__ __forceinline__ void unpk2(u64 v, float &lo, float &hi) {
    asm("mov.b64 {%0,%1}, %2;" : "=f"(lo), "=f"(hi) : "l"(v));
}

// ---------------------------------------------------------------------------
// Kernel 1: conv 3x3 (C->S) — R14 exact (best measured: 135.9us).
// ---------------------------------------------------------------------------
__global__ void __launch_bounds__(196, 4)
conv_kernel(const float* __restrict__ x,
            const float* __restrict__ wgt) {
    __shared__ float plane[4][PLANE_SZ];           // pairs: {0,1} and {2,3}
    __shared__ __align__(16) float wall[WALL_SZ];  // [ci][t][s]

    const int tid = threadIdx.x;
    const int b   = blockIdx.x / CGRP;
    const int g   = blockIdx.x % CGRP;
    const int c0  = g * CH_PER;

    for (int i = tid; i < PLANE_SZ; i += 196) {
        plane[0][i] = 0.f;
        plane[1][i] = 0.f;
        plane[2][i] = 0.f;
        plane[3][i] = 0.f;
    }

    for (int i = tid; i < WALL_SZ; i += 196) {
        int ci  = i / 72;
        int rem = i - ci * 72;
        int t   = rem >> 3;
        int s   = rem & 7;
        wall[i] = wgt[((size_t)s * CC + c0 + ci) * 9 + t];
    }

    const int r = tid / 7;                 // 0..27
    const int q = tid % 7;                 // cols 4q..4q+3
    const int wbase = r * PSTRIDE + 4 * q; // 16B aligned

    int ssofs[4];
#pragma unroll
    for (int k = 0; k < 4; k++) {
        int i = tid + k * 196;
        ssofs[k] = (i / 28 + 1) * PSTRIDE + (i % 28) + 1;
    }

    const float* xb = x + ((size_t)b * CC + c0) * HW;

    __syncthreads();   // zeroing complete before anyone stages interior cells

    {
        const float* xc0 = xb;
        const float* xc1 = xb + HW;
#pragma unroll
        for (int k = 0; k < 4; k++) {
            plane[0][ssofs[k]] = xc0[tid + k * 196];
            plane[1][ssofs[k]] = xc1[tid + k * 196];
        }
    }
    __syncthreads();   // also covers wall preload

    u64 acc[4][4];     // [pixel][region-pair]
#pragma unroll
    for (int px = 0; px < 4; px++)
#pragma unroll
        for (int sp = 0; sp < 4; sp++) acc[px][sp] = 0ull;

    for (int ci = 0; ci < CH_PER; ci += 2) {
        const int cur = (ci >> 1) & 1;
        const int nxt = cur ^ 1;
        const float* pl0 = plane[cur * 2];
        const float* pl1 = plane[cur * 2 + 1];

        float pref[8];
        const bool more = (ci + 2 < CH_PER);
        if (more) {
            const float* xc2 = xb + (size_t)(ci + 2) * HW;
            const float* xc3 = xb + (size_t)(ci + 3) * HW;
#pragma unroll
            for (int k = 0; k < 4; k++) {
                pref[k]     = xc2[tid + k * 196];
                pref[k + 4] = xc3[tid + k * 196];
            }
        }

#pragma unroll
        for (int half = 0; half < 2; half++) {
            const float* pl = (half == 0) ? pl0 : pl1;
            const float* wrow = &wall[(ci + half) * 72];
#pragma unroll
            for (int dr = 0; dr < 3; dr++) {
                const float* rp = &pl[wbase + dr * PSTRIDE];
                float4 f = *(const float4*)rp;
                float2 h = *(const float2*)(rp + 4);
                u64 dv[6];
                dv[0] = pk2(f.x, f.x);
                dv[1] = pk2(f.y, f.y);
                dv[2] = pk2(f.z, f.z);
                dv[3] = pk2(f.w, f.w);
                dv[4] = pk2(h.x, h.x);
                dv[5] = pk2(h.y, h.y);
#pragma unroll
                for (int tc = 0; tc < 3; tc++) {
                    const ulonglong2* wp =
                        (const ulonglong2*)&wrow[(dr * 3 + tc) * 8];
                    ulonglong2 wA = wp[0];
                    ulonglong2 wB = wp[1];
                    fma2(acc[0][0], dv[tc + 0], wA.x);
                    fma2(acc[0][1], dv[tc + 0], wA.y);
                    fma2(acc[0][2], dv[tc + 0], wB.x);
                    fma2(acc[0][3], dv[tc + 0], wB.y);
                    fma2(acc[1][0], dv[tc + 1], wA.x);
                    fma2(acc[1][1], dv[tc + 1], wA.y);
                    fma2(acc[1][2], dv[tc + 1], wB.x);
                    fma2(acc[1][3], dv[tc + 1], wB.y);
                    fma2(acc[2][0], dv[tc + 2], wA.x);
                    fma2(acc[2][1], dv[tc + 2], wA.y);
                    fma2(acc[2][2], dv[tc + 2], wB.x);
                    fma2(acc[2][3], dv[tc + 2], wB.y);
                    fma2(acc[3][0], dv[tc + 3], wA.x);
                    fma2(acc[3][1], dv[tc + 3], wA.y);
                    fma2(acc[3][2], dv[tc + 3], wB.x);
                    fma2(acc[3][3], dv[tc + 3], wB.y);
                }
            }
        }

        if (more) {
            float* nl0 = plane[nxt * 2];
            float* nl1 = plane[nxt * 2 + 1];
#pragma unroll
            for (int k = 0; k < 4; k++) {
                nl0[ssofs[k]] = pref[k];
                nl1[ssofs[k]] = pref[k + 4];
            }
        }
        __syncthreads();
    }

    float v[4][8];
#pragma unroll
    for (int px = 0; px < 4; px++)
#pragma unroll
        for (int sp = 0; sp < 4; sp++)
            unpk2(acc[px][sp], v[px][2 * sp], v[px][2 * sp + 1]);

    float* pb = g_partial + ((size_t)(g * BB + b) * SS) * HW;
    const int p0 = 4 * tid;
#pragma unroll
    for (int s = 0; s < 8; s++)
        *(float4*)&pb[s * HW + p0] =
            make_float4(v[0][s], v[1][s], v[2][s], v[3][s]);
}

// ---------------------------------------------------------------------------
// Kernel 2 (FUSED reduce+einsum): 2 CTAs per batch, 1024 threads.
// Phase A: mask[b] = bias + sum_g partial[g][b] in smem (chunk 0 writes out).
// Phase B (R16): pixel-pair vectorization — warp does 2 channels/pass,
// 6 passes; x via LDG.64 (2 adjacent px/lane), mask via LDS.64. Both are
// natural (p0,p1) u64 pairs -> fma2 with NO pk2 repacking. acc.lo = even
// px sum, acc.hi = odd px sum.
// ---------------------------------------------------------------------------
__global__ void __launch_bounds__(1024, 1)
einsum_fused_kernel(const float* __restrict__ x,
                    const float* __restrict__ bias,
                    float* __restrict__ mask,
                    float* __restrict__ learned) {
    __shared__ __align__(16) float msk[SS * HW];    // 25088 B

    const int tid   = threadIdx.x;
    const int b     = blockIdx.x >> 1;
    const int chunk = blockIdx.x & 1;

    // ---- Phase A: build mask in smem from partials + bias ----
    const float4* p4 = (const float4*)g_partial;
    const size_t gstride = (size_t)BB * (SS * HW / 4);
    float4* mout = (float4*)(mask + (size_t)b * SS * HW);
#pragma unroll
    for (int j4 = tid; j4 < SS * HW / 4; j4 += 1024) {
        int s = j4 / (HW / 4);
        float bv = bias[s];
        float4 a = make_float4(bv, bv, bv, bv);
        size_t base = (size_t)b * (SS * HW / 4) + j4;
#pragma unroll
        for (int g = 0; g < CGRP; g++) {
            float4 f = p4[base + (size_t)g * gstride];
            a.x += f.x; a.y += f.y; a.z += f.z; a.w += f.w;
        }
        ((float4*)msk)[j4] = a;
        if (chunk == 0) mout[j4] = a;
    }
    __syncthreads();

    // ---- Phase B: pixel-pair einsum ----
    const int warp = tid / 32, lane = tid % 32;
    const float inv = 1.0f / 784.0f;

    for (int pass = 0; pass < 6; pass++) {
        const int ch0 = chunk * 384 + warp * 12 + pass * 2;
        const u64* xc0 =
            (const u64*)(x + ((size_t)b * CC + ch0) * HW);
        const u64* xc1 =
            (const u64*)(x + ((size_t)b * CC + ch0 + 1) * HW);

        u64 acc[2][8];
#pragma unroll
        for (int s = 0; s < 8; s++) { acc[0][s] = 0ull; acc[1][s] = 0ull; }

        for (int i = 0; i < 12; i++) {      // unmasked: px 0..767
            int pc2 = i * 32 + lane;        // float2 index
            u64 xv0 = xc0[pc2];
            u64 xv1 = xc1[pc2];
#pragma unroll
            for (int s = 0; s < 8; s++) {
                u64 mv = *(const u64*)&msk[s * HW + 2 * pc2];
                fma2(acc[0][s], xv0, mv);
                fma2(acc[1][s], xv1, mv);
            }
        }
        {                                   // tail: px 768..783 (lanes 0..7)
            bool valid = lane < 8;
            int pc2 = valid ? (384 + lane) : 384;
            u64 xv0 = valid ? xc0[pc2] : 0ull;
            u64 xv1 = valid ? xc1[pc2] : 0ull;
#pragma unroll
            for (int s = 0; s < 8; s++) {
                u64 mv = *(const u64*)&msk[s * HW + 2 * pc2];
                fma2(acc[0][s], xv0, mv);
                fma2(acc[1][s], xv1, mv);
            }
        }

#pragma unroll
        for (int c = 0; c < 2; c++)
#pragma unroll
            for (int s = 0; s < 8; s++) {
                float lo, hi;
                unpk2(acc[c][s], lo, hi);
                float v = lo + hi;
#pragma unroll
                for (int o = 16; o > 0; o >>= 1)
                    v += __shfl_xor_sync(0xffffffffu, v, o);
                if (lane == 0)
                    learned[((size_t)b * CC + ch0 + c) * SS + s] = v * inv;
            }
    }
}

// ---------------------------------------------------------------------------
extern "C" void kernel_launch(void* const* d_in, const int* in_sizes, int n_in,
                              void* d_out, int out_size) {
    const float* x      = (const float*)d_in[0];
    const float* conv_w = (const float*)d_in[1];
    const float* conv_b = (const float*)d_in[2];

    float* out     = (float*)d_out;
    float* learned = out;                  // [B, C, S]
    float* mask    = out + LEARNED_SIZE;   // [B, S, H, W]

    conv_kernel<<<BB * CGRP, 196>>>(x, conv_w);
    einsum_fused_kernel<<<BB * 2, 1024>>>(x, conv_b, mask, learned);
}

// round 17
// speedup vs baseline: 1.7585x; 1.7585x over previous
#include <cuda_runtime.h>

#define BB 64
#define CC 768
#define SS 8
#define HH 28
#define WW 28
#define HW 784
#define LEARNED_SIZE (BB*CC*SS)   /* 393216 */
#define MASK_SIZE    (BB*SS*HW)   /* 401408 */

#define CGRP 16                   /* channel groups per batch for conv */
#define CH_PER (CC/CGRP)          /* 48 channels per CTA */

#define PSTRIDE 36                /* padded plane row stride */
#define PLANE_SZ (30*PSTRIDE)
#define WALL_SZ (CH_PER*72)       /* 3456 floats: [ci][t][s] */

typedef unsigned long long u64;

// partials: [CGRP][B][S][HW] — written with plain STG.128, reduced afterwards
__device__ float g_partial[(size_t)CGRP * BB * SS * HW];

__device__ __forceinline__ u64 pk2(float lo, float hi) {
    u64 r; asm("mov.b64 %0, {%1,%2};" : "=l"(r) : "f"(lo), "f"(hi)); return r;
}
__device__ __forceinline__ void fma2(u64 &d, u64 a, u64 b) {
    asm("fma.rn.f32x2 %0, %1, %2, %0;" : "+l"(d) : "l"(a), "l"(b));
}
__device__ __forceinline__ void unpk2(u64 v, float &lo, float &hi) {
    asm("mov.b64 {%0,%1}, %2;" : "=f"(lo), "=f"(hi) : "l"(v));
}

// ---------------------------------------------------------------------------
// Kernel 1: conv 3x3 (C->S) — R14 exact (best measured: 135.9us).
// ---------------------------------------------------------------------------
__global__ void __launch_bounds__(196, 4)
conv_kernel(const float* __restrict__ x,
            const float* __restrict__ wgt) {
    __shared__ float plane[4][PLANE_SZ];           // pairs: {0,1} and {2,3}
    __shared__ __align__(16) float wall[WALL_SZ];  // [ci][t][s]

    const int tid = threadIdx.x;
    const int b   = blockIdx.x / CGRP;
    const int g   = blockIdx.x % CGRP;
    const int c0  = g * CH_PER;

    for (int i = tid; i < PLANE_SZ; i += 196) {
        plane[0][i] = 0.f;
        plane[1][i] = 0.f;
        plane[2][i] = 0.f;
        plane[3][i] = 0.f;
    }

    for (int i = tid; i < WALL_SZ; i += 196) {
        int ci  = i / 72;
        int rem = i - ci * 72;
        int t   = rem >> 3;
        int s   = rem & 7;
        wall[i] = wgt[((size_t)s * CC + c0 + ci) * 9 + t];
    }

    const int r = tid / 7;                 // 0..27
    const int q = tid % 7;                 // cols 4q..4q+3
    const int wbase = r * PSTRIDE + 4 * q; // 16B aligned

    int ssofs[4];
#pragma unroll
    for (int k = 0; k < 4; k++) {
        int i = tid + k * 196;
        ssofs[k] = (i / 28 + 1) * PSTRIDE + (i % 28) + 1;
    }

    const float* xb = x + ((size_t)b * CC + c0) * HW;

    __syncthreads();   // zeroing complete before anyone stages interior cells

    {
        const float* xc0 = xb;
        const float* xc1 = xb + HW;
#pragma unroll
        for (int k = 0; k < 4; k++) {
            plane[0][ssofs[k]] = xc0[tid + k * 196];
            plane[1][ssofs[k]] = xc1[tid + k * 196];
        }
    }
    __syncthreads();   // also covers wall preload

    u64 acc[4][4];     // [pixel][region-pair]
#pragma unroll
    for (int px = 0; px < 4; px++)
#pragma unroll
        for (int sp = 0; sp < 4; sp++) acc[px][sp] = 0ull;

    for (int ci = 0; ci < CH_PER; ci += 2) {
        const int cur = (ci >> 1) & 1;
        const int nxt = cur ^ 1;
        const float* pl0 = plane[cur * 2];
        const float* pl1 = plane[cur * 2 + 1];

        float pref[8];
        const bool more = (ci + 2 < CH_PER);
        if (more) {
            const float* xc2 = xb + (size_t)(ci + 2) * HW;
            const float* xc3 = xb + (size_t)(ci + 3) * HW;
#pragma unroll
            for (int k = 0; k < 4; k++) {
                pref[k]     = xc2[tid + k * 196];
                pref[k + 4] = xc3[tid + k * 196];
            }
        }

#pragma unroll
        for (int half = 0; half < 2; half++) {
            const float* pl = (half == 0) ? pl0 : pl1;
            const float* wrow = &wall[(ci + half) * 72];
#pragma unroll
            for (int dr = 0; dr < 3; dr++) {
                const float* rp = &pl[wbase + dr * PSTRIDE];
                float4 f = *(const float4*)rp;
                float2 h = *(const float2*)(rp + 4);
                u64 dv[6];
                dv[0] = pk2(f.x, f.x);
                dv[1] = pk2(f.y, f.y);
                dv[2] = pk2(f.z, f.z);
                dv[3] = pk2(f.w, f.w);
                dv[4] = pk2(h.x, h.x);
                dv[5] = pk2(h.y, h.y);
#pragma unroll
                for (int tc = 0; tc < 3; tc++) {
                    const ulonglong2* wp =
                        (const ulonglong2*)&wrow[(dr * 3 + tc) * 8];
                    ulonglong2 wA = wp[0];
                    ulonglong2 wB = wp[1];
                    fma2(acc[0][0], dv[tc + 0], wA.x);
                    fma2(acc[0][1], dv[tc + 0], wA.y);
                    fma2(acc[0][2], dv[tc + 0], wB.x);
                    fma2(acc[0][3], dv[tc + 0], wB.y);
                    fma2(acc[1][0], dv[tc + 1], wA.x);
                    fma2(acc[1][1], dv[tc + 1], wA.y);
                    fma2(acc[1][2], dv[tc + 1], wB.x);
                    fma2(acc[1][3], dv[tc + 1], wB.y);
                    fma2(acc[2][0], dv[tc + 2], wA.x);
                    fma2(acc[2][1], dv[tc + 2], wA.y);
                    fma2(acc[2][2], dv[tc + 2], wB.x);
                    fma2(acc[2][3], dv[tc + 2], wB.y);
                    fma2(acc[3][0], dv[tc + 3], wA.x);
                    fma2(acc[3][1], dv[tc + 3], wA.y);
                    fma2(acc[3][2], dv[tc + 3], wB.x);
                    fma2(acc[3][3], dv[tc + 3], wB.y);
                }
            }
        }

        if (more) {
            float* nl0 = plane[nxt * 2];
            float* nl1 = plane[nxt * 2 + 1];
#pragma unroll
            for (int k = 0; k < 4; k++) {
                nl0[ssofs[k]] = pref[k];
                nl1[ssofs[k]] = pref[k + 4];
            }
        }
        __syncthreads();
    }

    float v[4][8];
#pragma unroll
    for (int px = 0; px < 4; px++)
#pragma unroll
        for (int sp = 0; sp < 4; sp++)
            unpk2(acc[px][sp], v[px][2 * sp], v[px][2 * sp + 1]);

    float* pb = g_partial + ((size_t)(g * BB + b) * SS) * HW;
    const int p0 = 4 * tid;
#pragma unroll
    for (int s = 0; s < 8; s++)
        *(float4*)&pb[s * HW + p0] =
            make_float4(v[0][s], v[1][s], v[2][s], v[3][s]);
}

// ---------------------------------------------------------------------------
// Kernel 2 (FUSED reduce+einsum): 2 CTAs per batch, 1024 threads.
// Phase A: mask[b] = bias + sum_g partial[g][b] in smem (chunk 0 writes out).
// Phase B: R15/R10-form inner loop (scalar LDG.32, 4-channel interleave,
// tail-split) + R17: one-iteration software prefetch of the 4 x-loads
// (8 outstanding LDGs). Butterfly+store inline per (c,s) to save registers.
// ---------------------------------------------------------------------------
__global__ void __launch_bounds__(1024, 1)
einsum_fused_kernel(const float* __restrict__ x,
                    const float* __restrict__ bias,
                    float* __restrict__ mask,
                    float* __restrict__ learned) {
    __shared__ float msk[SS * HW];          // 25088 B

    const int tid   = threadIdx.x;
    const int b     = blockIdx.x >> 1;
    const int chunk = blockIdx.x & 1;

    // ---- Phase A: build mask in smem from partials + bias ----
    const float4* p4 = (const float4*)g_partial;
    const size_t gstride = (size_t)BB * (SS * HW / 4);
    float4* mout = (float4*)(mask + (size_t)b * SS * HW);
#pragma unroll
    for (int j4 = tid; j4 < SS * HW / 4; j4 += 1024) {
        int s = j4 / (HW / 4);
        float bv = bias[s];
        float4 a = make_float4(bv, bv, bv, bv);
        size_t base = (size_t)b * (SS * HW / 4) + j4;
#pragma unroll
        for (int g = 0; g < CGRP; g++) {
            float4 f = p4[base + (size_t)g * gstride];
            a.x += f.x; a.y += f.y; a.z += f.z; a.w += f.w;
        }
        ((float4*)msk)[j4] = a;
        if (chunk == 0) mout[j4] = a;
    }
    __syncthreads();

    // ---- Phase B: einsum (R10 inner loop + 1-iter x prefetch) ----
    const int warp = tid / 32, lane = tid % 32;
    const float inv = 1.0f / 784.0f;

    for (int qd = 0; qd < 3; qd++) {
        const int ch0 = chunk * 384 + warp * 12 + qd * 4;
        const float* xb = x + ((size_t)b * CC + ch0) * HW;

        u64 acc[2][8];
#pragma unroll
        for (int s = 0; s < 8; s++) { acc[0][s] = 0ull; acc[1][s] = 0ull; }

        // prefetch iteration 0
        float nx0 = xb[lane];
        float nx1 = xb[HW + lane];
        float nx2 = xb[2 * HW + lane];
        float nx3 = xb[3 * HW + lane];

        for (int i = 0; i < 24; i++) {      // unmasked body: px 0..767
            float x0 = nx0, x1 = nx1, x2 = nx2, x3 = nx3;
            if (i < 23) {                   // prefetch i+1 (8 LDGs in flight)
                int pn = (i + 1) * 32 + lane;
                nx0 = xb[pn];
                nx1 = xb[HW + pn];
                nx2 = xb[2 * HW + pn];
                nx3 = xb[3 * HW + pn];
            }
            int pc = i * 32 + lane;
            u64 xp0 = pk2(x0, x1), xp1 = pk2(x2, x3);
#pragma unroll
            for (int s = 0; s < 8; s++) {
                float m = msk[s * HW + pc];
                u64 m2 = pk2(m, m);
                fma2(acc[0][s], xp0, m2);
                fma2(acc[1][s], xp1, m2);
            }
        }
        {                                   // tail: px 768..783 (lanes 0..15)
            bool valid = lane < 16;
            int pc = valid ? (768 + lane) : 768;
            float x0 = valid ? xb[pc]          : 0.f;
            float x1 = valid ? xb[HW + pc]     : 0.f;
            float x2 = valid ? xb[2 * HW + pc] : 0.f;
            float x3 = valid ? xb[3 * HW + pc] : 0.f;
            u64 xp0 = pk2(x0, x1), xp1 = pk2(x2, x3);
#pragma unroll
            for (int s = 0; s < 8; s++) {
                float m = msk[s * HW + pc];
                u64 m2 = pk2(m, m);
                fma2(acc[0][s], xp0, m2);
                fma2(acc[1][s], xp1, m2);
            }
        }

        // butterfly + store inline per (c,s) to keep register count low
#pragma unroll
        for (int h = 0; h < 2; h++)
#pragma unroll
            for (int s = 0; s < 8; s++) {
                float lo, hi;
                unpk2(acc[h][s], lo, hi);
#pragma unroll
                for (int o = 16; o > 0; o >>= 1) {
                    lo += __shfl_xor_sync(0xffffffffu, lo, o);
                    hi += __shfl_xor_sync(0xffffffffu, hi, o);
                }
                if (lane == 0) {
                    learned[((size_t)b * CC + ch0 + 2 * h) * SS + s] = lo * inv;
                    learned[((size_t)b * CC + ch0 + 2 * h + 1) * SS + s] = hi * inv;
                }
            }
    }
}

// ---------------------------------------------------------------------------
extern "C" void kernel_launch(void* const* d_in, const int* in_sizes, int n_in,
                              void* d_out, int out_size) {
    const float* x      = (const float*)d_in[0];
    const float* conv_w = (const float*)d_in[1];
    const float* conv_b = (const float*)d_in[2];

    float* out     = (float*)d_out;
    float* learned = out;                  // [B, C, S]
    float* mask    = out + LEARNED_SIZE;   // [B, S, H, W]

    conv_kernel<<<BB * CGRP, 196>>>(x, conv_w);
    einsum_fused_kernel<<<BB * 2, 1024>>>(x, conv_b, mask, learned);
}